// round 7
// baseline (speedup 1.0000x reference)
#include <cuda_runtime.h>
#include <cuda_bf16.h>

// RAM multi-step transformer — one CTA (256 threads) per TWO batch elements.
//  * grid 128 -> exactly <=1 CTA per SM (no 2:1 CTA imbalance)
//  * conn loads amortized across both batches (half the conn LDG traffic)
//  * 16 in / 8 state / 4 out table loads per thread, front-batched (deep MLP)
//  * L2 policy: mem_state = evict_last (its ~105MB touched-line set repeats
//    identically every graph replay and fits L2 alone), mem_in/mem_out =
//    evict_first (streamed).
//
// x: (256,1024) i32 | conn_in: (2048,16) | conn_state: (1024,16) | conn_out: (512,16)
// mem_in: (2048,65536) f32 | mem_state: (1024,65536) f32 | mem_out: (512,65536) f32
// out: (256,512) f32

#define BATCH 256
#define IN_BITS 1024
#define N_IN 2048
#define N_ST 1024
#define N_OUT 512
#define TBL 65536
#define MAX_ITERS 4
#define THREADS 256

__device__ __forceinline__ unsigned long long mk_policy_last() {
    unsigned long long pol;
    asm("createpolicy.fractional.L2::evict_last.b64 %0, 1.0;" : "=l"(pol));
    return pol;
}
__device__ __forceinline__ unsigned long long mk_policy_first() {
    unsigned long long pol;
    asm("createpolicy.fractional.L2::evict_first.b64 %0, 1.0;" : "=l"(pol));
    return pol;
}
__device__ __forceinline__ float ld_hint(const float* p, unsigned long long pol) {
    float v;
    asm("ld.global.nc.L2::cache_hint.f32 %0, [%1], %2;" : "=f"(v) : "l"(p), "l"(pol));
    return v;
}

// 16-bit address from packed bit-words in shared memory.
__device__ __forceinline__ unsigned gather16(const unsigned* __restrict__ sw,
                                             int4 c0, int4 c1, int4 c2, int4 c3) {
    unsigned a = 0;
    a |= ((sw[c0.x >> 5] >> (c0.x & 31)) & 1u) << 0;
    a |= ((sw[c0.y >> 5] >> (c0.y & 31)) & 1u) << 1;
    a |= ((sw[c0.z >> 5] >> (c0.z & 31)) & 1u) << 2;
    a |= ((sw[c0.w >> 5] >> (c0.w & 31)) & 1u) << 3;
    a |= ((sw[c1.x >> 5] >> (c1.x & 31)) & 1u) << 4;
    a |= ((sw[c1.y >> 5] >> (c1.y & 31)) & 1u) << 5;
    a |= ((sw[c1.z >> 5] >> (c1.z & 31)) & 1u) << 6;
    a |= ((sw[c1.w >> 5] >> (c1.w & 31)) & 1u) << 7;
    a |= ((sw[c2.x >> 5] >> (c2.x & 31)) & 1u) << 8;
    a |= ((sw[c2.y >> 5] >> (c2.y & 31)) & 1u) << 9;
    a |= ((sw[c2.z >> 5] >> (c2.z & 31)) & 1u) << 10;
    a |= ((sw[c2.w >> 5] >> (c2.w & 31)) & 1u) << 11;
    a |= ((sw[c3.x >> 5] >> (c3.x & 31)) & 1u) << 12;
    a |= ((sw[c3.y >> 5] >> (c3.y & 31)) & 1u) << 13;
    a |= ((sw[c3.z >> 5] >> (c3.z & 31)) & 1u) << 14;
    a |= ((sw[c3.w >> 5] >> (c3.w & 31)) & 1u) << 15;
    return a;
}

__global__ __launch_bounds__(THREADS, 1)
void ram_multistep_kernel(
    const int* __restrict__ x,
    const int4* __restrict__ conn_in,
    const int4* __restrict__ conn_state,
    const int4* __restrict__ conn_out,
    const float* __restrict__ mem_in,
    const float* __restrict__ mem_state,
    const float* __restrict__ mem_out,
    float* __restrict__ out)
{
    __shared__ unsigned sx[2][32];       // packed input bits, per batch
    __shared__ unsigned sbufA[2][96];    // [0,64) in-bits, [64,96) state bits
    __shared__ unsigned sbufB[2][96];    // double buffer

    const int b0 = blockIdx.x * 2;       // two batches per CTA
    const int tid = threadIdx.x;
    const int lane = tid & 31;
    const int warp = tid >> 5;           // 0..7

    const unsigned long long pol_state = mk_policy_last();
    const unsigned long long pol_io    = mk_policy_first();

    // ---- Pack x bits for both batches ----
    #pragma unroll
    for (int bb = 0; bb < 2; bb++) {
        #pragma unroll
        for (int r = 0; r < 4; r++) {
            int bit = __ldg(x + (b0 + bb) * IN_BITS + r * 256 + tid);
            unsigned w = __ballot_sync(0xFFFFFFFFu, bit != 0);
            if (lane == 0) sx[bb][r * 8 + warp] = w;
        }
    }
    if (tid < 64) sbufA[tid >> 5][64 + (tid & 31)] = 0u;   // initial state = 0
    __syncthreads();

    // ---- Input layer: 2048 neurons x 2 batches, conn loaded once per neuron ----
    {
        unsigned addrA[8], addrB[8];
        #pragma unroll
        for (int r = 0; r < 8; r++) {
            int n = r * 256 + tid;
            const int4* c = conn_in + n * 4;
            int4 c0 = __ldg(c + 0), c1 = __ldg(c + 1), c2 = __ldg(c + 2), c3 = __ldg(c + 3);
            addrA[r] = gather16(sx[0], c0, c1, c2, c3);
            addrB[r] = gather16(sx[1], c0, c1, c2, c3);
        }
        float vA[8], vB[8];
        #pragma unroll
        for (int r = 0; r < 8; r++) {
            const float* row = mem_in + (size_t)(r * 256 + tid) * TBL;
            vA[r] = ld_hint(row + addrA[r], pol_io);
            vB[r] = ld_hint(row + addrB[r], pol_io);
        }
        #pragma unroll
        for (int r = 0; r < 8; r++) {
            unsigned wA = __ballot_sync(0xFFFFFFFFu, vA[r] > 0.5f);
            unsigned wB = __ballot_sync(0xFFFFFFFFu, vB[r] > 0.5f);
            if (lane == 0) {
                sbufA[0][r * 8 + warp] = wA; sbufB[0][r * 8 + warp] = wA;
                sbufA[1][r * 8 + warp] = wB; sbufB[1][r * 8 + warp] = wB;
            }
        }
    }
    __syncthreads();

    // ---- Recurrent state iterations: 4 neurons x 2 batches per thread ----
    unsigned (*cur)[96] = sbufA;
    unsigned (*nxt)[96] = sbufB;
    for (int it = 0; it < MAX_ITERS; it++) {
        unsigned addrA[4], addrB[4];
        #pragma unroll
        for (int k = 0; k < 4; k++) {
            int n = k * 256 + tid;
            const int4* c = conn_state + n * 4;
            int4 c0 = __ldg(c + 0), c1 = __ldg(c + 1), c2 = __ldg(c + 2), c3 = __ldg(c + 3);
            addrA[k] = gather16(cur[0], c0, c1, c2, c3);
            addrB[k] = gather16(cur[1], c0, c1, c2, c3);
        }
        float vA[4], vB[4];
        #pragma unroll
        for (int k = 0; k < 4; k++) {
            const float* row = mem_state + (size_t)(k * 256 + tid) * TBL;
            vA[k] = ld_hint(row + addrA[k], pol_state);
            vB[k] = ld_hint(row + addrB[k], pol_state);
        }
        #pragma unroll
        for (int k = 0; k < 4; k++) {
            unsigned wA = __ballot_sync(0xFFFFFFFFu, vA[k] > 0.5f);
            unsigned wB = __ballot_sync(0xFFFFFFFFu, vB[k] > 0.5f);
            if (lane == 0) {
                nxt[0][64 + k * 8 + warp] = wA;   // disjoint from cur: no pre-barrier
                nxt[1][64 + k * 8 + warp] = wB;
            }
        }
        __syncthreads();                 // nxt complete & visible
        unsigned (*t)[96] = cur; cur = nxt; nxt = t;
    }

    // ---- Output layer: 2 neurons x 2 batches per thread (final state only) ----
    {
        unsigned addrA[2], addrB[2];
        #pragma unroll
        for (int r = 0; r < 2; r++) {
            int n = r * 256 + tid;
            const int4* c = conn_out + n * 4;
            int4 c0 = __ldg(c + 0), c1 = __ldg(c + 1), c2 = __ldg(c + 2), c3 = __ldg(c + 3);
            addrA[r] = gather16(cur[0], c0, c1, c2, c3);
            addrB[r] = gather16(cur[1], c0, c1, c2, c3);
        }
        #pragma unroll
        for (int r = 0; r < 2; r++) {
            int n = r * 256 + tid;
            const float* row = mem_out + (size_t)n * TBL;
            out[b0 * N_OUT + n]       = ld_hint(row + addrA[r], pol_io);
            out[(b0 + 1) * N_OUT + n] = ld_hint(row + addrB[r], pol_io);
        }
    }
}

extern "C" void kernel_launch(void* const* d_in, const int* in_sizes, int n_in,
                              void* d_out, int out_size) {
    const int* x            = (const int*)d_in[0];
    const int4* conn_in     = (const int4*)d_in[1];
    const int4* conn_state  = (const int4*)d_in[2];
    const int4* conn_out    = (const int4*)d_in[3];
    const float* mem_in     = (const float*)d_in[4];
    const float* mem_state  = (const float*)d_in[5];
    const float* mem_out    = (const float*)d_in[6];
    float* out = (float*)d_out;

    ram_multistep_kernel<<<BATCH / 2, THREADS>>>(x, conn_in, conn_state, conn_out,
                                                 mem_in, mem_state, mem_out, out);
}

// round 8
// speedup vs baseline: 1.1740x; 1.1740x over previous
#include <cuda_runtime.h>
#include <cuda_bf16.h>

// RAM multi-step transformer — single kernel, one CTA (256 threads) per batch
// (round-6 structure, best so far). Cross-replay L2 retention tuning:
//  * mem_in / mem_out: evict_last 1.0  (80MB touched set, pinned)
//  * mem_state: fractional evict_last 0.25 / evict_first remainder
//    (~32MB of its 128MB touched set pinned STABLY across graph replays —
//     addresses are deterministic, so the same lines hit every replay;
//     the rest streams without displacing the pinned set)
//  Total pinned target ~112MB < 126MB L2.
//
// x: (256,1024) i32 | conn_in: (2048,16) | conn_state: (1024,16) | conn_out: (512,16)
// mem_in: (2048,65536) f32 | mem_state: (1024,65536) f32 | mem_out: (512,65536) f32
// out: (256,512) f32

#define BATCH 256
#define IN_BITS 1024
#define N_IN 2048
#define N_ST 1024
#define N_OUT 512
#define TBL 65536
#define MAX_ITERS 4
#define THREADS 256

__device__ __forceinline__ unsigned long long mk_policy_pin() {
    unsigned long long pol;
    asm("createpolicy.fractional.L2::evict_last.b64 %0, 1.0;" : "=l"(pol));
    return pol;
}
__device__ __forceinline__ unsigned long long mk_policy_state() {
    unsigned long long pol;
    asm("createpolicy.fractional.L2::evict_last.L2::evict_first.b64 %0, 0.25;" : "=l"(pol));
    return pol;
}
__device__ __forceinline__ float ld_hint(const float* p, unsigned long long pol) {
    float v;
    asm("ld.global.nc.L2::cache_hint.f32 %0, [%1], %2;" : "=f"(v) : "l"(p), "l"(pol));
    return v;
}

// 16-bit address from packed bit-words in shared memory.
__device__ __forceinline__ unsigned gather16(const unsigned* __restrict__ sw,
                                             int4 c0, int4 c1, int4 c2, int4 c3) {
    unsigned a = 0;
    a |= ((sw[c0.x >> 5] >> (c0.x & 31)) & 1u) << 0;
    a |= ((sw[c0.y >> 5] >> (c0.y & 31)) & 1u) << 1;
    a |= ((sw[c0.z >> 5] >> (c0.z & 31)) & 1u) << 2;
    a |= ((sw[c0.w >> 5] >> (c0.w & 31)) & 1u) << 3;
    a |= ((sw[c1.x >> 5] >> (c1.x & 31)) & 1u) << 4;
    a |= ((sw[c1.y >> 5] >> (c1.y & 31)) & 1u) << 5;
    a |= ((sw[c1.z >> 5] >> (c1.z & 31)) & 1u) << 6;
    a |= ((sw[c1.w >> 5] >> (c1.w & 31)) & 1u) << 7;
    a |= ((sw[c2.x >> 5] >> (c2.x & 31)) & 1u) << 8;
    a |= ((sw[c2.y >> 5] >> (c2.y & 31)) & 1u) << 9;
    a |= ((sw[c2.z >> 5] >> (c2.z & 31)) & 1u) << 10;
    a |= ((sw[c2.w >> 5] >> (c2.w & 31)) & 1u) << 11;
    a |= ((sw[c3.x >> 5] >> (c3.x & 31)) & 1u) << 12;
    a |= ((sw[c3.y >> 5] >> (c3.y & 31)) & 1u) << 13;
    a |= ((sw[c3.z >> 5] >> (c3.z & 31)) & 1u) << 14;
    a |= ((sw[c3.w >> 5] >> (c3.w & 31)) & 1u) << 15;
    return a;
}

__global__ __launch_bounds__(THREADS, 2)
void ram_multistep_kernel(
    const int* __restrict__ x,
    const int4* __restrict__ conn_in,
    const int4* __restrict__ conn_state,
    const int4* __restrict__ conn_out,
    const float* __restrict__ mem_in,
    const float* __restrict__ mem_state,
    const float* __restrict__ mem_out,
    float* __restrict__ out)
{
    __shared__ unsigned sx[32];       // 1024 input bits packed
    __shared__ unsigned sbufA[96];    // [0,64) in-bits, [64,96) state bits
    __shared__ unsigned sbufB[96];    // double buffer

    const int b = blockIdx.x;
    const int tid = threadIdx.x;
    const int lane = tid & 31;
    const int warp = tid >> 5;        // 0..7

    const unsigned long long pol_pin   = mk_policy_pin();
    const unsigned long long pol_state = mk_policy_state();

    // ---- Pack x bits (coalesced, ballot) ----
    #pragma unroll
    for (int r = 0; r < 4; r++) {
        int bit = __ldg(x + b * IN_BITS + r * 256 + tid);
        unsigned w = __ballot_sync(0xFFFFFFFFu, bit != 0);
        if (lane == 0) sx[r * 8 + warp] = w;
    }
    if (tid < 32) sbufA[64 + tid] = 0u;    // initial state = 0 (read by iter 0)
    __syncthreads();

    // ---- Input layer: 2048 neurons, 8 per thread, addr batch then load batch ----
    {
        unsigned addr[8];
        #pragma unroll
        for (int r = 0; r < 8; r++) {
            int n = r * 256 + tid;
            const int4* c = conn_in + n * 4;
            int4 c0 = __ldg(c + 0), c1 = __ldg(c + 1), c2 = __ldg(c + 2), c3 = __ldg(c + 3);
            addr[r] = gather16(sx, c0, c1, c2, c3);
        }
        float v[8];
        #pragma unroll
        for (int r = 0; r < 8; r++) {
            int n = r * 256 + tid;
            v[r] = ld_hint(mem_in + (size_t)n * TBL + addr[r], pol_pin);
        }
        #pragma unroll
        for (int r = 0; r < 8; r++) {
            unsigned w = __ballot_sync(0xFFFFFFFFu, v[r] > 0.5f);
            if (lane == 0) { sbufA[r * 8 + warp] = w; sbufB[r * 8 + warp] = w; }
        }
    }
    __syncthreads();

    // ---- Recurrent state iterations: 4 per thread, double-buffered, 1 barrier/iter ----
    unsigned* cur = sbufA;
    unsigned* nxt = sbufB;
    for (int it = 0; it < MAX_ITERS; it++) {
        unsigned addr[4];
        #pragma unroll
        for (int k = 0; k < 4; k++) {
            int n = k * 256 + tid;
            const int4* c = conn_state + n * 4;
            int4 c0 = __ldg(c + 0), c1 = __ldg(c + 1), c2 = __ldg(c + 2), c3 = __ldg(c + 3);
            addr[k] = gather16(cur, c0, c1, c2, c3);
        }
        float v[4];
        #pragma unroll
        for (int k = 0; k < 4; k++) {
            int n = k * 256 + tid;
            v[k] = ld_hint(mem_state + (size_t)n * TBL + addr[k], pol_state);
        }
        #pragma unroll
        for (int k = 0; k < 4; k++) {
            unsigned w = __ballot_sync(0xFFFFFFFFu, v[k] > 0.5f);
            if (lane == 0) nxt[64 + k * 8 + warp] = w;   // disjoint from cur: no pre-barrier
        }
        __syncthreads();                 // nxt complete & visible
        unsigned* t = cur; cur = nxt; nxt = t;
    }

    // ---- Output layer: 512 neurons, 2 per thread (final state only) ----
    {
        unsigned addr[2];
        #pragma unroll
        for (int r = 0; r < 2; r++) {
            int n = r * 256 + tid;
            const int4* c = conn_out + n * 4;
            int4 c0 = __ldg(c + 0), c1 = __ldg(c + 1), c2 = __ldg(c + 2), c3 = __ldg(c + 3);
            addr[r] = gather16(cur, c0, c1, c2, c3);
        }
        #pragma unroll
        for (int r = 0; r < 2; r++) {
            int n = r * 256 + tid;
            out[b * N_OUT + n] = ld_hint(mem_out + (size_t)n * TBL + addr[r], pol_pin);
        }
    }
}

extern "C" void kernel_launch(void* const* d_in, const int* in_sizes, int n_in,
                              void* d_out, int out_size) {
    const int* x            = (const int*)d_in[0];
    const int4* conn_in     = (const int4*)d_in[1];
    const int4* conn_state  = (const int4*)d_in[2];
    const int4* conn_out    = (const int4*)d_in[3];
    const float* mem_in     = (const float*)d_in[4];
    const float* mem_state  = (const float*)d_in[5];
    const float* mem_out    = (const float*)d_in[6];
    float* out = (float*)d_out;

    ram_multistep_kernel<<<BATCH, THREADS>>>(x, conn_in, conn_state, conn_out,
                                             mem_in, mem_state, mem_out, out);
}